// round 14
// baseline (speedup 1.0000x reference)
#include <cuda_runtime.h>

// Problem constants (fixed shapes)
#define BB 4
#define CC 16
#define TT 2048
#define FF 32
#define JJ 256
#define KK 2049          // MAX_T + 1 (odd kernel)
#define HALF 1024
#define RGROUP 4
#define NGROUP 8
#define NSLOT 33         // total conv chunks per (b,c)
#define MAXCHUNK 136     // max taps per chunk (g6: 135)
#define BUFOFF 4

#define TWO_PI_F 6.28318530717958647692f
#define PI_F     3.14159265358979f
#define PI_2_F   1.57079632679490f

typedef unsigned long long ull;

// Scratch (device globals; no allocation allowed)
__device__ ulonglong2 g_wav4[BB*NGROUP*KK*2];       // [b][g][m][2]: 4 rows' (wr,wi), 32B/tap
__device__ float      g_psum[BB*FF];                // |w| sums (window-only)
__device__ float4     g_Vp[(size_t)BB*CC*NSLOT*RGROUP*JJ]; // conv chunk partials (v0,v1)

// Chunk schedule, ~120-tap chunks from worst-case L at 6-sigma (fs=500):
// taps {2049,671,373,259,199,161,135,117}
__constant__ int c_nchunk[NGROUP] = {16,6,3,2,2,2,1,1};
__constant__ int c_cbase [NGROUP] = {0,16,22,25,27,29,31,32};
__constant__ int c_slot_g[NSLOT]  = {0,0,0,0,0,0,0,0,0,0,0,0,0,0,0,0, 1,1,1,1,1,1, 2,2,2, 3,3, 4,4, 5,5, 6, 7};
__constant__ int c_slot_k[NSLOT]  = {0,1,2,3,4,5,6,7,8,9,10,11,12,13,14,15, 0,1,2,3,4,5, 0,1,2, 0,1, 0,1, 0,1, 0, 0};

// ---- packed f32x2 helpers -------------------------------------------------
__device__ __forceinline__ ull ffma2(ull a, ull b, ull c) {
    ull d; asm("fma.rn.f32x2 %0, %1, %2, %3;" : "=l"(d) : "l"(a), "l"(b), "l"(c));
    return d;
}
__device__ __forceinline__ ull pack2(float v) {
    ull d; asm("mov.b64 %0, {%1, %1};" : "=l"(d) : "f"(v));
    return d;
}
__device__ __forceinline__ float2 unpack2(ull v) {
    float2 r; asm("mov.b64 {%0, %1}, %2;" : "=f"(r.x), "=f"(r.y) : "l"(v));
    return r;
}

__device__ __forceinline__ float compute_gx(int j, int seq) {
    // steps = jnp.linspace(0,1,256): steps[j] = fl(j * fl(1/255)), endpoint -> 1.0
    float step255 = __fdiv_rn(1.0f, 255.0f);
    float stepj   = (j == 255) ? 1.0f : __fmul_rn((float)j, step255);
    float q    = __fdiv_rn(__fmul_rn(2.0f, (float)(seq - 1)), 2047.0f);
    float endx = __fadd_rn(-1.0f, q);
    float a    = __fadd_rn(endx, 1.0f);
    float xco  = __fadd_rn(-1.0f, __fmul_rn(stepj, a));
    return __fmul_rn(__fmul_rn(__fadd_rn(xco, 1.0f), 0.5f), 2047.0f);
}

// 6-sigma truncation half-width for group g (largest-sigma row = g*4)
__device__ __forceinline__ int group_L(int g, float fsb,
                                       const float* __restrict__ freqs,
                                       const float* __restrict__ ncyc) {
    float fc = fmaxf(freqs[g * RGROUP], 0.1f);
    float nc = fmaxf(ncyc[g * RGROUP], 1.0f);
    float sig = nc * fsb / (TWO_PI_F * fc);   // sigma in samples
    int L = (int)(6.0f * sig) + 1;            // dropped mass ~2e-9
    return min(L, HALF);
}

// A&S 4.4.49 atan poly on [0,1] (abs err ~2e-8) -> atan2
__device__ __forceinline__ float fast_atan2(float y, float x) {
    float ax = fabsf(x), ay = fabsf(y);
    float mx = fmaxf(ax, ay), mn = fminf(ax, ay);
    float z  = __fdiv_rn(mn, mx);     // NaN if both 0 (fixed below)
    float t  = z * z;
    float p  = -0.0161657367f + t * 0.0028662257f;
    p = fmaf(p, t,  0.0429096138f);
    p = fmaf(p, t, -0.0752896400f);
    p = fmaf(p, t,  0.1065626393f);
    p = fmaf(p, t, -0.1420889944f);
    p = fmaf(p, t,  0.1999355085f);
    p = fmaf(p, t, -0.3333314528f);
    p = fmaf(p, t,  1.0f);
    p = p * z;
    if (ay > ax)   p = PI_2_F - p;
    if (x < 0.0f)  p = PI_F - p;
    p = copysignf(p, y);
    if (mx == 0.0f) p = 0.0f;         // atan2(0,0) = 0
    return p;
}

// ---------------------------------------------------------------------------
// Kernel 1: Morlet taps over the 6-sigma window only. Norm = sum |w| over the
// window (outside: |w| = env < 1.5e-8 peak, dropped mass ~2e-9 -> pure scale
// on mag, phase invariant). One block per (b,f).
// ---------------------------------------------------------------------------
__global__ void __launch_bounds__(256) k_wavelet(
    const float* __restrict__ fs,
    const float* __restrict__ freqs,
    const float* __restrict__ ncyc)
{
    int bf = blockIdx.x;            // b*32 + f
    int b = bf >> 5, f = bf & 31;
    float fc  = fmaxf(freqs[f], 0.1f);
    float nc  = fmaxf(ncyc[f], 1.0f);
    float fsb = fs[b];
    float omega = __fmul_rn(TWO_PI_F, fc);
    float sigma = __fdiv_rn(nc, omega);
    float d2    = __fmul_rn(2.0f, __fmul_rn(sigma, sigma));

    int g = f >> 2, r = f & 3;
    int Lw = min(group_L(g, fsb, freqs, ncyc) + 2, HALF);  // write window + guard

    __shared__ float sred[256];
    float part = 0.0f;

    float2* wbase = (float2*)&g_wav4[((size_t)(b * NGROUP + g) * KK) * 2];

    for (int k = HALF - Lw + threadIdx.x; k <= HALF + Lw; k += 256) {
        float t   = (float)(k - HALF);
        float ts  = __fdiv_rn(t, fsb);
        float t2  = __fmul_rn(ts, ts);
        float q   = __fdiv_rn(-t2, d2);
        float env = expf(q);
        float arg = __fmul_rn(omega, ts);
        float cs  = cosf(arg);
        float sn  = sinf(arg);
        float wr  = __fmul_rn(cs, env);
        float wi  = __fmul_rn(sn, env);
        wbase[k * 4 + r] = make_float2(wr, wi);
        part += sqrtf(__fadd_rn(__fmul_rn(wr, wr), __fmul_rn(wi, wi)));
    }
    sred[threadIdx.x] = part;
    __syncthreads();
    for (int o = 128; o > 0; o >>= 1) {
        if (threadIdx.x < o) sred[threadIdx.x] = __fadd_rn(sred[threadIdx.x], sred[threadIdx.x + o]);
        __syncthreads();
    }
    if (threadIdx.x == 0) g_psum[bf] = sred[0];
}

// ---------------------------------------------------------------------------
// Kernel 2: chunked sampled convolution (packed f32x2, single-level acc).
// x staged over the chunk's REACHABLE range only: t in [lo, 2047+hi], i.e.
// u = t - lo + BUFOFF <= 2051 + clen <= 2187 (+3 vec overshoot; SKEW<2470).
// ---------------------------------------------------------------------------
#define SKEW(a) ((a) + ((a) >> 3))

__global__ void __launch_bounds__(256, 4) k_conv(
    const float* __restrict__ x,
    const float* __restrict__ fs,
    const int*   __restrict__ seq_lens,
    const float* __restrict__ freqs,
    const float* __restrict__ ncyc)
{
    const int slot = blockIdx.x;    // 0..32
    const int c    = blockIdx.y;
    const int b    = blockIdx.z;
    const int g    = c_slot_g[slot];
    const int kk   = c_slot_k[slot];

    __shared__ float      xs[2500];           // skewed window buffer
    __shared__ ulonglong2 ws[2 * MAXCHUNK];   // staged weight chunk (32B/tap)

    const float fsb = fs[b];
    int L = group_L(g, fsb, freqs, ncyc);

    int taps = 2 * L + 1;
    int ncks = c_nchunk[g];
    int W  = (taps + ncks - 1) / ncks;
    int lo = -L + kk * W;
    int hi = min(lo + W, L + 1);
    int clen = hi - lo;                      // <= MAXCHUNK

    // ---- stage weight chunk ----
    {
        const float4* src = (const float4*)(g_wav4 + ((size_t)(b * NGROUP + g) * KK + (HALF + lo)) * 2);
        float4* dst = (float4*)ws;
        int n4 = clen * 2;
        for (int i = threadIdx.x; i < n4; i += 256) dst[i] = src[i];
    }

    // ---- x window: u(t) = t - lo + BUFOFF, needed t in [lo, 2047+hi] ----
    const float4* xrow4 = (const float4*)(x + ((size_t)b * CC + c) * TT);
    int t4s = max(0, lo) >> 2;
    int t_hi = min(TT - 1, TT - 1 + hi);     // clamp upper fill (hi<0 chunks!)
    int t4e = (t_hi >> 2) + 1;               // exclusive float4 bound
    for (int t4 = t4s + threadIdx.x; t4 < t4e; t4 += 256) {
        float4 v = xrow4[t4];
        int u0 = 4 * t4 - lo + BUFOFF;
        xs[SKEW(u0    )] = v.x;
        xs[SKEW(u0 + 1)] = v.y;
        xs[SKEW(u0 + 2)] = v.z;
        xs[SKEW(u0 + 3)] = v.w;
    }
    if (lo < 0) {                            // left zero pad: t in [lo, -1]
        for (int i = threadIdx.x; i < -lo; i += 256) {
            int u = i + BUFOFF;
            xs[SKEW(u)] = 0.0f;
        }
    }
    if (hi >= 0) {                           // right zero pad: t in [2048, 2048+hi]
        for (int d = threadIdx.x; d <= hi; d += 256) {
            int u = TT + d - lo + BUFOFF;
            xs[SKEW(u)] = 0.0f;
        }
    }
    __syncthreads();

    const int j   = threadIdx.x;
    const int seq = seq_lens[b];
    float gx = compute_gx(j, seq);
    int t0 = (int)floorf(gx);

    ull sum[8];
#pragma unroll
    for (int i = 0; i < 8; i++) sum[i] = 0ull;

    int a = t0 + BUFOFF;                     // u at m = lo
    const ulonglong2* wsp = ws;
    float xv0 = xs[SKEW(a)];

#pragma unroll 8
    for (int i = 0; i < clen; ++i) {
        int a1 = a + 1;
        float xv1 = xs[SKEW(a1)];
        ull p0 = pack2(xv0);
        ull p1 = pack2(xv1);
        ulonglong2 wa = wsp[0];
        ulonglong2 wb = wsp[1];
        sum[0] = ffma2(wa.x, p0, sum[0]);
        sum[1] = ffma2(wa.x, p1, sum[1]);
        sum[2] = ffma2(wa.y, p0, sum[2]);
        sum[3] = ffma2(wa.y, p1, sum[3]);
        sum[4] = ffma2(wb.x, p0, sum[4]);
        sum[5] = ffma2(wb.x, p1, sum[5]);
        sum[6] = ffma2(wb.y, p0, sum[6]);
        sum[7] = ffma2(wb.y, p1, sum[7]);
        xv0 = xv1; a = a1; wsp += 2;
    }

    // store partials: [b][c][slot][r][j] as float4 (v0.x, v0.y, v1.x, v1.y)
#pragma unroll
    for (int r = 0; r < RGROUP; r++) {
        float2 v0 = unpack2(sum[r * 2 + 0]);
        float2 v1 = unpack2(sum[r * 2 + 1]);
        size_t base = (((size_t)(b * CC + c) * NSLOT + slot) * RGROUP + r) * JJ + j;
        g_Vp[base] = make_float4(v0.x, v0.y, v1.x, v1.y);
    }
}

// ---------------------------------------------------------------------------
// Kernel 3: each thread reduces ONE row's chunk partials, exchanges via smem,
// then does bilinear + mag/phase. Grid (JJ/8, BB*CC), 256 thr = 32 rows x 8 tok.
// ---------------------------------------------------------------------------
__global__ void __launch_bounds__(256) k_out(
    const int* __restrict__ seq_lens,
    float* __restrict__ out)
{
    int bc = blockIdx.y;           // b*CC + c
    int b = bc >> 4, c = bc & 15;
    int tid = threadIdx.x;
    int f  = tid >> 3;             // row 0..31 (each warp = one 4-row group)
    int jj = tid & 7;
    int j  = blockIdx.x * 8 + jj;

    __shared__ float s0x[289], s0y[289], s1x[289], s1y[289];

    int seq = seq_lens[b];
    float gx  = compute_gx(j, seq);
    float x0f = floorf(gx);
    int t0 = (int)x0f;
    int zero_x1 = (t0 + 1 >= TT);

    // ---- phase 1: reduce row f at token j ----
    {
        int g = f >> 2, r = f & 3;
        float norm = __fadd_rn(g_psum[b * FF + f], 1e-8f);

        float2 s0 = make_float2(0.0f, 0.0f);
        float2 s1 = make_float2(0.0f, 0.0f);
        int ncks = c_nchunk[g], cb = c_cbase[g];
        for (int k = 0; k < ncks; ++k) {
            size_t base = (((size_t)(b * CC + c) * NSLOT + (cb + k)) * RGROUP + r) * JJ + j;
            float4 v = g_Vp[base];
            s0.x = __fadd_rn(s0.x, v.x);  s0.y = __fadd_rn(s0.y, v.y);
            s1.x = __fadd_rn(s1.x, v.z);  s1.y = __fadd_rn(s1.y, v.w);
        }
        if (zero_x1) s1 = make_float2(0.0f, 0.0f);
        int si = f * 9 + jj;
        s0x[si] = __fdiv_rn(s0.x, norm);
        s0y[si] = __fdiv_rn(s0.y, norm);
        s1x[si] = __fdiv_rn(s1.x, norm);
        s1y[si] = __fdiv_rn(s1.y, norm);
    }
    __syncthreads();

    // ---- phase 2: output element (f, j) ----
    // y coordinate — linspace(-1,1,32): fl(-1 + f*fl(2/31)), endpoint 1.0
    float stepy = __fdiv_rn(2.0f, 31.0f);
    float ylin  = (f == 31) ? 1.0f : __fadd_rn(-1.0f, __fmul_rn((float)f, stepy));
    float gyp   = __fmul_rn(__fmul_rn(__fadd_rn(ylin, 1.0f), 0.5f), 31.0f);
    float y0f   = floorf(gyp);
    float wy1   = __fadd_rn(gyp, -y0f);
    float wy0   = __fadd_rn(1.0f, -wy1);
    int y0 = (int)y0f;
    int y1 = y0 + 1;
    float val1 = (y1 <= FF - 1) ? 1.0f : 0.0f;
    int y1c = min(y1, FF - 1);
    int y0c = min(max(y0, 0), FF - 1);

    float wx1 = __fadd_rn(gx, -x0f);
    float wx0 = __fadd_rn(1.0f, -wx1);

    int si0 = y0c * 9 + jj;
    int si1 = y1c * 9 + jj;
    float2 v00 = make_float2(s0x[si0], s0y[si0]);
    float2 v01 = make_float2(s1x[si0], s1y[si0]);
    float2 v10 = make_float2(s0x[si1], s0y[si1]);
    float2 v11 = make_float2(s1x[si1], s1y[si1]);

    // reference order: ((g00*w00 + g01*w01) + g10*w10) + g11*w11
    float vr = __fadd_rn(__fadd_rn(__fadd_rn(
                 __fmul_rn(v00.x, __fmul_rn(wy0, wx0)),
                 __fmul_rn(v01.x, __fmul_rn(wy0, wx1))),
                 __fmul_rn(__fmul_rn(v10.x, val1), __fmul_rn(wy1, wx0))),
                 __fmul_rn(__fmul_rn(v11.x, val1), __fmul_rn(wy1, wx1)));
    float vi = __fadd_rn(__fadd_rn(__fadd_rn(
                 __fmul_rn(v00.y, __fmul_rn(wy0, wx0)),
                 __fmul_rn(v01.y, __fmul_rn(wy0, wx1))),
                 __fmul_rn(__fmul_rn(v10.y, val1), __fmul_rn(wy1, wx0))),
                 __fmul_rn(__fmul_rn(v11.y, val1), __fmul_rn(wy1, wx1)));

    float mag = sqrtf(__fadd_rn(__fadd_rn(__fmul_rn(vr, vr), __fmul_rn(vi, vi)), 1e-8f));
    float ph  = __fdiv_rn(fast_atan2(vi, vr), PI_F);

    size_t ob = (((size_t)(b * CC + c) * 2 + 0) * FF + f) * JJ + j;
    out[ob] = mag;
    out[ob + (size_t)FF * JJ] = ph;
}

// ---------------------------------------------------------------------------
extern "C" void kernel_launch(void* const* d_in, const int* in_sizes, int n_in,
                              void* d_out, int out_size)
{
    const float* x        = (const float*)d_in[0];  // (4,16,2048)
    const float* fs       = (const float*)d_in[1];  // (4,)
    const int*   seq_lens = (const int*)  d_in[2];  // (4,)
    const float* freqs    = (const float*)d_in[3];  // (32,)
    const float* ncyc     = (const float*)d_in[4];  // (32,)
    float* out = (float*)d_out;                     // (4,16,2,32,256)

    k_wavelet<<<BB * FF, 256>>>(fs, freqs, ncyc);
    k_conv<<<dim3(NSLOT, CC, BB), 256>>>(x, fs, seq_lens, freqs, ncyc);
    k_out<<<dim3(JJ / 8, BB * CC), 256>>>(seq_lens, out);
}

// round 16
// speedup vs baseline: 1.0042x; 1.0042x over previous
#include <cuda_runtime.h>

// Problem constants (fixed shapes)
#define BB 4
#define CC 16
#define TT 2048
#define FF 32
#define JJ 256
#define KK 2049          // MAX_T + 1 (odd kernel)
#define HALF 1024
#define RGROUP 4
#define NGROUP 8
#define NSLOT 33         // total conv chunks per (b,c)
#define MAXCHUNK 136     // max taps per chunk
#define BUFOFF 4

#define TWO_PI_F 6.28318530717958647692f
#define PI_F     3.14159265358979f
#define PI_2_F   1.57079632679490f

typedef unsigned long long ull;

// Scratch (device globals; no allocation allowed)
__device__ float  g_psum[BB*FF];                            // |w| norm sums
__device__ float4 g_Vp[(size_t)BB*CC*NSLOT*RGROUP*JJ];      // conv chunk partials (v0,v1)

// Chunk schedule, ~120-tap chunks from worst-case L at 6-sigma (fs=500):
// taps {2049,671,373,259,199,161,135,117}
__constant__ int c_nchunk[NGROUP] = {16,6,3,2,2,2,1,1};
__constant__ int c_cbase [NGROUP] = {0,16,22,25,27,29,31,32};
__constant__ int c_slot_g[NSLOT]  = {0,0,0,0,0,0,0,0,0,0,0,0,0,0,0,0, 1,1,1,1,1,1, 2,2,2, 3,3, 4,4, 5,5, 6, 7};
__constant__ int c_slot_k[NSLOT]  = {0,1,2,3,4,5,6,7,8,9,10,11,12,13,14,15, 0,1,2,3,4,5, 0,1,2, 0,1, 0,1, 0,1, 0, 0};

// ---- packed f32x2 helpers -------------------------------------------------
__device__ __forceinline__ ull ffma2(ull a, ull b, ull c) {
    ull d; asm("fma.rn.f32x2 %0, %1, %2, %3;" : "=l"(d) : "l"(a), "l"(b), "l"(c));
    return d;
}
__device__ __forceinline__ ull pack2(float v) {
    ull d; asm("mov.b64 %0, {%1, %1};" : "=l"(d) : "f"(v));
    return d;
}
__device__ __forceinline__ float2 unpack2(ull v) {
    float2 r; asm("mov.b64 {%0, %1}, %2;" : "=f"(r.x), "=f"(r.y) : "l"(v));
    return r;
}

__device__ __forceinline__ float compute_gx(int j, int seq) {
    // steps = jnp.linspace(0,1,256): steps[j] = fl(j * fl(1/255)), endpoint -> 1.0
    float step255 = __fdiv_rn(1.0f, 255.0f);
    float stepj   = (j == 255) ? 1.0f : __fmul_rn((float)j, step255);
    float q    = __fdiv_rn(__fmul_rn(2.0f, (float)(seq - 1)), 2047.0f);
    float endx = __fadd_rn(-1.0f, q);
    float a    = __fadd_rn(endx, 1.0f);
    float xco  = __fadd_rn(-1.0f, __fmul_rn(stepj, a));
    return __fmul_rn(__fmul_rn(__fadd_rn(xco, 1.0f), 0.5f), 2047.0f);
}

// 6-sigma truncation half-width for group g (largest-sigma row = g*4)
__device__ __forceinline__ int group_L(int g, float fsb,
                                       const float* __restrict__ freqs,
                                       const float* __restrict__ ncyc) {
    float fc = fmaxf(freqs[g * RGROUP], 0.1f);
    float nc = fmaxf(ncyc[g * RGROUP], 1.0f);
    float sig = nc * fsb / (TWO_PI_F * fc);   // sigma in samples
    int L = (int)(6.0f * sig) + 1;            // dropped mass ~2e-9
    return min(L, HALF);
}

// A&S 4.4.49 atan poly on [0,1] (abs err ~2e-8) -> atan2
__device__ __forceinline__ float fast_atan2(float y, float x) {
    float ax = fabsf(x), ay = fabsf(y);
    float mx = fmaxf(ax, ay), mn = fminf(ax, ay);
    float z  = __fdiv_rn(mn, mx);     // NaN if both 0 (fixed below)
    float t  = z * z;
    float p  = -0.0161657367f + t * 0.0028662257f;
    p = fmaf(p, t,  0.0429096138f);
    p = fmaf(p, t, -0.0752896400f);
    p = fmaf(p, t,  0.1065626393f);
    p = fmaf(p, t, -0.1420889944f);
    p = fmaf(p, t,  0.1999355085f);
    p = fmaf(p, t, -0.3333314528f);
    p = fmaf(p, t,  1.0f);
    p = p * z;
    if (ay > ax)   p = PI_2_F - p;
    if (x < 0.0f)  p = PI_F - p;
    p = copysignf(p, y);
    if (mx == 0.0f) p = 0.0f;         // atan2(0,0) = 0
    return p;
}

// ---------------------------------------------------------------------------
// Kernel 1: norm only. |w| = env * sqrt(cos^2+sin^2) = env (exact in reals;
// fp deviation ~1e-8 relative after summing). Norm scales re and im equally
// -> phase exactly invariant, mag shift ~1e-8. Full 2049-tap range, no trig.
// ---------------------------------------------------------------------------
__global__ void __launch_bounds__(256) k_norm(
    const float* __restrict__ fs,
    const float* __restrict__ freqs,
    const float* __restrict__ ncyc)
{
    int bf = blockIdx.x;            // b*32 + f
    int b = bf >> 5, f = bf & 31;
    float fc  = fmaxf(freqs[f], 0.1f);
    float nc  = fmaxf(ncyc[f], 1.0f);
    float fsb = fs[b];
    float omega = __fmul_rn(TWO_PI_F, fc);
    float sigma = __fdiv_rn(nc, omega);
    float d2    = __fmul_rn(2.0f, __fmul_rn(sigma, sigma));

    __shared__ float sred[256];
    float part = 0.0f;
    for (int k = threadIdx.x; k < KK; k += 256) {
        float t   = (float)(k - HALF);
        float ts  = __fdiv_rn(t, fsb);
        float t2  = __fmul_rn(ts, ts);
        float q   = __fdiv_rn(-t2, d2);
        part += expf(q);
    }
    sred[threadIdx.x] = part;
    __syncthreads();
    for (int o = 128; o > 0; o >>= 1) {
        if (threadIdx.x < o) sred[threadIdx.x] = __fadd_rn(sred[threadIdx.x], sred[threadIdx.x + o]);
        __syncthreads();
    }
    if (threadIdx.x == 0) g_psum[bf] = sred[0];
}

// ---------------------------------------------------------------------------
// Kernel 2: chunked sampled convolution (packed f32x2, single-level acc).
// The weight chunk (<=136 taps x 4 rows) is GENERATED in-block into smem
// (same per-tap fp op sequence as the old table kernel), overlapped with the
// x-row loads. x staged over the chunk's reachable range only.
// ---------------------------------------------------------------------------
#define SKEW(a) ((a) + ((a) >> 3))

__global__ void __launch_bounds__(256, 4) k_conv(
    const float* __restrict__ x,
    const float* __restrict__ fs,
    const int*   __restrict__ seq_lens,
    const float* __restrict__ freqs,
    const float* __restrict__ ncyc)
{
    const int slot = blockIdx.x;    // 0..32
    const int c    = blockIdx.y;
    const int b    = blockIdx.z;
    const int g    = c_slot_g[slot];
    const int kk   = c_slot_k[slot];

    __shared__ float      xs[2500];           // skewed window buffer
    __shared__ ulonglong2 ws[2 * MAXCHUNK];   // weight chunk (32B/tap)

    const float fsb = fs[b];
    int L = group_L(g, fsb, freqs, ncyc);

    int taps = 2 * L + 1;
    int ncks = c_nchunk[g];
    int W  = (taps + ncks - 1) / ncks;
    int lo = -L + kk * W;
    int hi = min(lo + W, L + 1);
    int clen = hi - lo;                      // <= MAXCHUNK

    // ---- generate weight chunk in-block: element e -> (tap, row) ----
    {
        float2* fws = (float2*)ws;           // fws[tap*4 + row] = (wr, wi)
        int nElem = clen * RGROUP;
        for (int e = threadIdx.x; e < nElem; e += 256) {
            int ti = e >> 2;
            int r  = e & 3;
            int f  = g * RGROUP + r;
            float fc  = fmaxf(freqs[f], 0.1f);
            float nc  = fmaxf(ncyc[f], 1.0f);
            float omega = __fmul_rn(TWO_PI_F, fc);
            float sigma = __fdiv_rn(nc, omega);
            float d2    = __fmul_rn(2.0f, __fmul_rn(sigma, sigma));
            float t   = (float)(lo + ti);
            float ts  = __fdiv_rn(t, fsb);
            float t2  = __fmul_rn(ts, ts);
            float q   = __fdiv_rn(-t2, d2);
            float env = expf(q);
            float arg = __fmul_rn(omega, ts);
            float cs  = cosf(arg);
            float sn  = sinf(arg);
            fws[ti * 4 + r] = make_float2(__fmul_rn(cs, env), __fmul_rn(sn, env));
        }
    }

    // ---- x window: u(t) = t - lo + BUFOFF, needed t in [lo, 2047+hi] ----
    const float4* xrow4 = (const float4*)(x + ((size_t)b * CC + c) * TT);
    int t4s = max(0, lo) >> 2;
    int t_hi = min(TT - 1, TT - 1 + hi);     // clamp upper fill (hi<0 chunks!)
    int t4e = (t_hi >> 2) + 1;               // exclusive float4 bound
    for (int t4 = t4s + threadIdx.x; t4 < t4e; t4 += 256) {
        float4 v = xrow4[t4];
        int u0 = 4 * t4 - lo + BUFOFF;
        xs[SKEW(u0    )] = v.x;
        xs[SKEW(u0 + 1)] = v.y;
        xs[SKEW(u0 + 2)] = v.z;
        xs[SKEW(u0 + 3)] = v.w;
    }
    if (lo < 0) {                            // left zero pad: t in [lo, -1]
        for (int i = threadIdx.x; i < -lo; i += 256) {
            int u = i + BUFOFF;
            xs[SKEW(u)] = 0.0f;
        }
    }
    if (hi >= 0) {                           // right zero pad: t in [2048, 2048+hi]
        for (int d = threadIdx.x; d <= hi; d += 256) {
            int u = TT + d - lo + BUFOFF;
            xs[SKEW(u)] = 0.0f;
        }
    }
    __syncthreads();

    const int j   = threadIdx.x;
    const int seq = seq_lens[b];
    float gx = compute_gx(j, seq);
    int t0 = (int)floorf(gx);

    ull sum[8];
#pragma unroll
    for (int i = 0; i < 8; i++) sum[i] = 0ull;

    int a = t0 + BUFOFF;                     // u at m = lo
    const ulonglong2* wsp = ws;
    float xv0 = xs[SKEW(a)];

#pragma unroll 8
    for (int i = 0; i < clen; ++i) {
        int a1 = a + 1;
        float xv1 = xs[SKEW(a1)];
        ull p0 = pack2(xv0);
        ull p1 = pack2(xv1);
        ulonglong2 wa = wsp[0];
        ulonglong2 wb = wsp[1];
        sum[0] = ffma2(wa.x, p0, sum[0]);
        sum[1] = ffma2(wa.x, p1, sum[1]);
        sum[2] = ffma2(wa.y, p0, sum[2]);
        sum[3] = ffma2(wa.y, p1, sum[3]);
        sum[4] = ffma2(wb.x, p0, sum[4]);
        sum[5] = ffma2(wb.x, p1, sum[5]);
        sum[6] = ffma2(wb.y, p0, sum[6]);
        sum[7] = ffma2(wb.y, p1, sum[7]);
        xv0 = xv1; a = a1; wsp += 2;
    }

    // store partials: [b][c][slot][r][j] as float4 (v0.x, v0.y, v1.x, v1.y)
#pragma unroll
    for (int r = 0; r < RGROUP; r++) {
        float2 v0 = unpack2(sum[r * 2 + 0]);
        float2 v1 = unpack2(sum[r * 2 + 1]);
        size_t base = (((size_t)(b * CC + c) * NSLOT + slot) * RGROUP + r) * JJ + j;
        g_Vp[base] = make_float4(v0.x, v0.y, v1.x, v1.y);
    }
}

// ---------------------------------------------------------------------------
// Kernel 3: each thread reduces ONE row's chunk partials, exchanges via smem,
// then does bilinear + mag/phase. Grid (JJ/8, BB*CC), 256 thr = 32 rows x 8 tok.
// ---------------------------------------------------------------------------
__global__ void __launch_bounds__(256) k_out(
    const int* __restrict__ seq_lens,
    float* __restrict__ out)
{
    int bc = blockIdx.y;           // b*CC + c
    int b = bc >> 4, c = bc & 15;
    int tid = threadIdx.x;
    int f  = tid >> 3;             // row 0..31 (each warp = one 4-row group)
    int jj = tid & 7;
    int j  = blockIdx.x * 8 + jj;

    __shared__ float s0x[289], s0y[289], s1x[289], s1y[289];

    int seq = seq_lens[b];
    float gx  = compute_gx(j, seq);
    float x0f = floorf(gx);
    int t0 = (int)x0f;
    int zero_x1 = (t0 + 1 >= TT);

    // ---- phase 1: reduce row f at token j ----
    {
        int g = f >> 2, r = f & 3;
        float norm = __fadd_rn(g_psum[b * FF + f], 1e-8f);

        float2 s0 = make_float2(0.0f, 0.0f);
        float2 s1 = make_float2(0.0f, 0.0f);
        int ncks = c_nchunk[g], cb = c_cbase[g];
        for (int k = 0; k < ncks; ++k) {
            size_t base = (((size_t)(b * CC + c) * NSLOT + (cb + k)) * RGROUP + r) * JJ + j;
            float4 v = g_Vp[base];
            s0.x = __fadd_rn(s0.x, v.x);  s0.y = __fadd_rn(s0.y, v.y);
            s1.x = __fadd_rn(s1.x, v.z);  s1.y = __fadd_rn(s1.y, v.w);
        }
        if (zero_x1) s1 = make_float2(0.0f, 0.0f);
        int si = f * 9 + jj;
        s0x[si] = __fdiv_rn(s0.x, norm);
        s0y[si] = __fdiv_rn(s0.y, norm);
        s1x[si] = __fdiv_rn(s1.x, norm);
        s1y[si] = __fdiv_rn(s1.y, norm);
    }
    __syncthreads();

    // ---- phase 2: output element (f, j) ----
    // y coordinate — linspace(-1,1,32): fl(-1 + f*fl(2/31)), endpoint 1.0
    float stepy = __fdiv_rn(2.0f, 31.0f);
    float ylin  = (f == 31) ? 1.0f : __fadd_rn(-1.0f, __fmul_rn((float)f, stepy));
    float gyp   = __fmul_rn(__fmul_rn(__fadd_rn(ylin, 1.0f), 0.5f), 31.0f);
    float y0f   = floorf(gyp);
    float wy1   = __fadd_rn(gyp, -y0f);
    float wy0   = __fadd_rn(1.0f, -wy1);
    int y0 = (int)y0f;
    int y1 = y0 + 1;
    float val1 = (y1 <= FF - 1) ? 1.0f : 0.0f;
    int y1c = min(y1, FF - 1);
    int y0c = min(max(y0, 0), FF - 1);

    float wx1 = __fadd_rn(gx, -x0f);
    float wx0 = __fadd_rn(1.0f, -wx1);

    int si0 = y0c * 9 + jj;
    int si1 = y1c * 9 + jj;
    float2 v00 = make_float2(s0x[si0], s0y[si0]);
    float2 v01 = make_float2(s1x[si0], s1y[si0]);
    float2 v10 = make_float2(s0x[si1], s0y[si1]);
    float2 v11 = make_float2(s1x[si1], s1y[si1]);

    // reference order: ((g00*w00 + g01*w01) + g10*w10) + g11*w11
    float vr = __fadd_rn(__fadd_rn(__fadd_rn(
                 __fmul_rn(v00.x, __fmul_rn(wy0, wx0)),
                 __fmul_rn(v01.x, __fmul_rn(wy0, wx1))),
                 __fmul_rn(__fmul_rn(v10.x, val1), __fmul_rn(wy1, wx0))),
                 __fmul_rn(__fmul_rn(v11.x, val1), __fmul_rn(wy1, wx1)));
    float vi = __fadd_rn(__fadd_rn(__fadd_rn(
                 __fmul_rn(v00.y, __fmul_rn(wy0, wx0)),
                 __fmul_rn(v01.y, __fmul_rn(wy0, wx1))),
                 __fmul_rn(__fmul_rn(v10.y, val1), __fmul_rn(wy1, wx0))),
                 __fmul_rn(__fmul_rn(v11.y, val1), __fmul_rn(wy1, wx1)));

    float mag = sqrtf(__fadd_rn(__fadd_rn(__fmul_rn(vr, vr), __fmul_rn(vi, vi)), 1e-8f));
    float ph  = __fdiv_rn(fast_atan2(vi, vr), PI_F);

    size_t ob = (((size_t)(b * CC + c) * 2 + 0) * FF + f) * JJ + j;
    out[ob] = mag;
    out[ob + (size_t)FF * JJ] = ph;
}

// ---------------------------------------------------------------------------
extern "C" void kernel_launch(void* const* d_in, const int* in_sizes, int n_in,
                              void* d_out, int out_size)
{
    const float* x        = (const float*)d_in[0];  // (4,16,2048)
    const float* fs       = (const float*)d_in[1];  // (4,)
    const int*   seq_lens = (const int*)  d_in[2];  // (4,)
    const float* freqs    = (const float*)d_in[3];  // (32,)
    const float* ncyc     = (const float*)d_in[4];  // (32,)
    float* out = (float*)d_out;                     // (4,16,2,32,256)

    k_norm<<<BB * FF, 256>>>(fs, freqs, ncyc);
    k_conv<<<dim3(NSLOT, CC, BB), 256>>>(x, fs, seq_lens, freqs, ncyc);
    k_out<<<dim3(JJ / 8, BB * CC), 256>>>(seq_lens, out);
}